// round 12
// baseline (speedup 1.0000x reference)
#include <cuda_runtime.h>
#include <cuda_fp16.h>
#include <cstdint>

// ---------------------------------------------------------------------------
// LightGCN forward: out = (x + A'x + A'(A'x)) / 3
// per-edge norm (row->col): dis[row]*dis[col], dis = rsqrt(indeg) or 0.
// N = 150000, D = 64 fp32, E = 2,000,000 ([2,E], int64 OR int32, runtime-
// detected). Single full-width pass. fp32 accumulation lives in d_out
// (v4-REDG scatter); BOTH convs gather in fp16 from one shared 19.2 MB
// buffer (xh before conv1, yh before conv2 — lifetimes disjoint).
// Scratch ~20.4 MB (proven-safe; 39.6 MB trips the harness mem check).
// ---------------------------------------------------------------------------

#define MAXN 150016

// Scratch: ~20.4 MB total.
__device__ int   g_shift;              // 1 if edge dtype int64, 0 if int32
__device__ float g_deg[MAXN];
__device__ float g_dis[MAXN];
__device__ uint2 g_h[MAXN * 16];       // fp16x4 gather buffer (x, then y), 19.2 MB

// ---------------------------------------------------------------------------
// Detect edge dtype: int64 node ids (<2^31) have zero high words; int32 pairs
// have a random nonzero second component almost surely.
__global__ void k_detect(const int2* __restrict__ p, int npairs) {
    __shared__ int nz;
    if (threadIdx.x == 0) nz = 0;
    __syncthreads();
    int local = 0;
    for (int i = threadIdx.x; i < npairs; i += blockDim.x)
        if (p[i].y != 0) local = 1;
    if (local) atomicOr(&nz, 1);
    __syncthreads();
    if (threadIdx.x == 0) g_shift = (nz == 0) ? 1 : 0;
}

__device__ __forceinline__ unsigned load_idx(const int* __restrict__ p32,
                                             long long pos, int shift) {
    return (unsigned)p32[pos << shift];
}

__device__ __forceinline__ uint2 f4_to_h4(float4 v) {
    __half2 h0 = __floats2half2_rn(v.x, v.y);
    __half2 h1 = __floats2half2_rn(v.z, v.w);
    uint2 r;
    r.x = *(const unsigned*)&h0;
    r.y = *(const unsigned*)&h1;
    return r;
}

__device__ __forceinline__ float4 h4_to_f4(uint2 h) {
    float2 f0 = __half22float2(*(const __half2*)&h.x);
    float2 f1 = __half22float2(*(const __half2*)&h.y);
    return make_float4(f0.x, f0.y, f1.x, f1.y);
}

// xh = fp16(x); also zero g_deg (fused — grid covers n4 > N).
__global__ void k_xh(const float4* __restrict__ x, int n4, int N) {
    int i = blockIdx.x * blockDim.x + threadIdx.x;
    if (i < N) g_deg[i] = 0.0f;
    if (i < n4) g_h[i] = f4_to_h4(__ldg(&x[i]));
}

__global__ void k_deg(const int* __restrict__ e32, int E, int N) {
    int i = blockIdx.x * blockDim.x + threadIdx.x;
    if (i >= E) return;
    int sh = g_shift;
    unsigned col = load_idx(e32, (long long)E + i, sh);
    if (col < (unsigned)N) atomicAdd(&g_deg[col], 1.0f);
}

__global__ void k_dis(int N) {
    int i = blockIdx.x * blockDim.x + threadIdx.x;
    if (i >= N) return;
    float d = g_deg[i];
    g_dis[i] = (d > 0.0f) ? rsqrtf(d) : 0.0f;
}

__global__ void k_zero_out(float4* __restrict__ out, int n4) {
    int i = blockIdx.x * blockDim.x + threadIdx.x;
    if (i < n4) out[i] = make_float4(0.f, 0.f, 0.f, 0.f);
}

// conv: out[col] += h[row] * nr.  16 lanes/edge, one fp16x4 (8B) gather each
// (128B/edge) + one v4-REDG fp32 scatter (256B/edge). nr includes the /3 for
// conv2 (scale parameter).
__global__ void __launch_bounds__(512) k_conv(
        float4* __restrict__ out, const int* __restrict__ e32,
        int E, int N, float scale) {
    long long t = (long long)blockIdx.x * blockDim.x + threadIdx.x;
    long long e = t >> 4;
    if (e >= E) return;
    int c = (int)(t & 15);

    int sh = g_shift;
    unsigned row = load_idx(e32, e, sh);
    unsigned col = load_idx(e32, (long long)E + e, sh);
    if (row >= (unsigned)N || col >= (unsigned)N) return;

    float nr = __ldg(&g_dis[row]) * __ldg(&g_dis[col]) * scale;

    uint2 h = __ldg(&g_h[(size_t)row * 16 + c]);
    float4 v = h4_to_f4(h);
    v.x *= nr; v.y *= nr; v.z *= nr; v.w *= nr;

    float4* pd = &out[(size_t)col * 16 + c];
    asm volatile("red.global.add.v4.f32 [%0], {%1, %2, %3, %4};"
                 :: "l"(pd), "f"(v.x), "f"(v.y), "f"(v.z), "f"(v.w)
                 : "memory");
}

// mid (fused): y = out (fp32 accum); overwrite g_h with fp16(y) for conv2's
// gather; rewrite out = (x + y) / 3.
__global__ void k_mid(const float4* __restrict__ x, float4* __restrict__ out,
                      int n4) {
    int i = blockIdx.x * blockDim.x + threadIdx.x;
    if (i >= n4) return;
    float4 y = out[i];
    g_h[i] = f4_to_h4(y);
    float4 a = __ldg(&x[i]);
    const float s = 1.0f / 3.0f;
    out[i] = make_float4((a.x + y.x) * s, (a.y + y.y) * s,
                         (a.z + y.z) * s, (a.w + y.w) * s);
}

// ---------------------------------------------------------------------------
extern "C" void kernel_launch(void* const* d_in, const int* in_sizes, int n_in,
                              void* d_out, int out_size) {
    // Input-order detection: x has N*64 = 9.6M elements; edge_index has
    // 2E = 4M elements. x is strictly larger.
    int ix = 0, ie = 1;
    if (n_in >= 2 && in_sizes[0] < in_sizes[1]) { ix = 1; ie = 0; }

    const float4* x   = (const float4*)d_in[ix];
    const int*    e32 = (const int*)d_in[ie];
    float4*       out = (float4*)d_out;

    int N = in_sizes[ix] / 64;
    int E = in_sizes[ie] / 2;
    if (N > MAXN) N = MAXN;

    const int TB = 256;
    const int CB = 512;                      // conv block size
    const int n4 = N * 16;
    const int gO = (n4 + TB - 1) / TB;
    const int gN = (N + TB - 1) / TB;
    const int gE1 = (E + TB - 1) / TB;
    const long long workE = (long long)E * 16;
    const int gE16 = (int)((workE + CB - 1) / CB);

    // dtype detect (reads <=8KB — in bounds under both interpretations)
    {
        int npairs = E;
        if (npairs > 1024) npairs = 1024;
        k_detect<<<1, 256>>>((const int2*)e32, npairs);
    }

    // xh = fp16(x) (+ zero deg), degrees, normalization
    k_xh<<<gO, TB>>>(x, n4, N);
    k_deg<<<gE1, TB>>>(e32, E, N);
    k_dis<<<gN, TB>>>(N);

    // y = A'x accumulated in fp32 directly in out (gather from fp16 xh)
    k_zero_out<<<gO, TB>>>(out, n4);
    k_conv<<<gE16, CB>>>(out, e32, E, N, 1.0f);

    // fp16(y) replaces xh in g_h; out = (x + y) / 3
    k_mid<<<gO, TB>>>(x, out, n4);

    // out += A'(y) / 3 (gather from fp16 yh)
    k_conv<<<gE16, CB>>>(out, e32, E, N, 1.0f / 3.0f);
}

// round 13
// speedup vs baseline: 1.1092x; 1.1092x over previous
#include <cuda_runtime.h>
#include <cuda_fp16.h>
#include <cstdint>

// ---------------------------------------------------------------------------
// LightGCN forward: out = (x + A'x + A'(A'x)) / 3
// per-edge norm (row->col): dis[row]*dis[col], dis = rsqrt(indeg) or 0.
// N = 150000, D = 64 fp32, E = 2,000,000 ([2,E], int64 OR int32, runtime-
// detected). Single full-width pass:
//   conv1: out += A'x          (fp32 gather + fp32 v4-REDG, round-11 proven)
//   conv2: g_h += fp16(A'y)    (fp32 gather from out, fp16 v2.f16x2 RED —
//                               halves the binding scatter-RMW stream)
//   final: out = (x + y + z)/3
// Scratch ~20.4 MB (proven-safe; 39.6 MB trips the harness mem check).
// ---------------------------------------------------------------------------

#define MAXN 150016

// Scratch: ~20.4 MB total.
__device__ int   g_shift;              // 1 if edge dtype int64, 0 if int32
__device__ float g_deg[MAXN];
__device__ float g_dis[MAXN];
__device__ uint2 g_h[MAXN * 16];       // fp16x4 accumulator for z=A'y, 19.2 MB

// ---------------------------------------------------------------------------
// Detect edge dtype: int64 node ids (<2^31) have zero high words; int32 pairs
// have a random nonzero second component almost surely.
__global__ void k_detect(const int2* __restrict__ p, int npairs) {
    __shared__ int nz;
    if (threadIdx.x == 0) nz = 0;
    __syncthreads();
    int local = 0;
    for (int i = threadIdx.x; i < npairs; i += blockDim.x)
        if (p[i].y != 0) local = 1;
    if (local) atomicOr(&nz, 1);
    __syncthreads();
    if (threadIdx.x == 0) g_shift = (nz == 0) ? 1 : 0;
}

__device__ __forceinline__ unsigned load_idx(const int* __restrict__ p32,
                                             long long pos, int shift) {
    return (unsigned)p32[pos << shift];
}

__device__ __forceinline__ float4 h4_to_f4(uint2 h) {
    float2 f0 = __half22float2(*(const __half2*)&h.x);
    float2 f1 = __half22float2(*(const __half2*)&h.y);
    return make_float4(f0.x, f0.y, f1.x, f1.y);
}

// One fused zero pass: out (38.4MB), g_h (19.2MB), deg (0.6MB).
__global__ void k_zero(float4* __restrict__ out, int n4, int N) {
    int i = blockIdx.x * blockDim.x + threadIdx.x;
    if (i < N) g_deg[i] = 0.0f;
    if (i < n4) {
        out[i] = make_float4(0.f, 0.f, 0.f, 0.f);
        g_h[i] = make_uint2(0u, 0u);
    }
}

__global__ void k_deg(const int* __restrict__ e32, int E, int N) {
    int i = blockIdx.x * blockDim.x + threadIdx.x;
    if (i >= E) return;
    int sh = g_shift;
    unsigned col = load_idx(e32, (long long)E + i, sh);
    if (col < (unsigned)N) atomicAdd(&g_deg[col], 1.0f);
}

__global__ void k_dis(int N) {
    int i = blockIdx.x * blockDim.x + threadIdx.x;
    if (i >= N) return;
    float d = g_deg[i];
    g_dis[i] = (d > 0.0f) ? rsqrtf(d) : 0.0f;
}

// conv1: out[col] += x[row] * nr, full 64 dims. 16 lanes/edge, one float4
// each: 256B coalesced gather + 256B fp32 v4-REDG scatter. (Round-11 proven.)
__global__ void __launch_bounds__(256) k_conv1(
        const float4* __restrict__ x, float4* __restrict__ out,
        const int* __restrict__ e32, int E, int N) {
    long long t = (long long)blockIdx.x * blockDim.x + threadIdx.x;
    long long e = t >> 4;
    if (e >= E) return;
    int c = (int)(t & 15);

    int sh = g_shift;
    unsigned row = load_idx(e32, e, sh);
    unsigned col = load_idx(e32, (long long)E + e, sh);
    if (row >= (unsigned)N || col >= (unsigned)N) return;

    float nr = __ldg(&g_dis[row]) * __ldg(&g_dis[col]);
    float4 v = __ldg(&x[(size_t)row * 16 + c]);
    v.x *= nr; v.y *= nr; v.z *= nr; v.w *= nr;

    float4* pd = &out[(size_t)col * 16 + c];
    asm volatile("red.global.add.v4.f32 [%0], {%1, %2, %3, %4};"
                 :: "l"(pd), "f"(v.x), "f"(v.y), "f"(v.z), "f"(v.w)
                 : "memory");
}

// conv2: z[col] += fp16(y[row] * nr). Gather y fp32 from out (256B/edge),
// scatter 8B fp16x4 per lane (128B/edge RMW — half of conv1's).
__global__ void __launch_bounds__(256) k_conv2(
        const float4* __restrict__ y, const int* __restrict__ e32,
        int E, int N) {
    long long t = (long long)blockIdx.x * blockDim.x + threadIdx.x;
    long long e = t >> 4;
    if (e >= E) return;
    int c = (int)(t & 15);

    int sh = g_shift;
    unsigned row = load_idx(e32, e, sh);
    unsigned col = load_idx(e32, (long long)E + e, sh);
    if (row >= (unsigned)N || col >= (unsigned)N) return;

    float nr = __ldg(&g_dis[row]) * __ldg(&g_dis[col]);
    float4 v = __ldg(&y[(size_t)row * 16 + c]);

    __half2 h0 = __floats2half2_rn(v.x * nr, v.y * nr);
    __half2 h1 = __floats2half2_rn(v.z * nr, v.w * nr);
    unsigned u0 = *(const unsigned*)&h0;
    unsigned u1 = *(const unsigned*)&h1;

    uint2* pd = &g_h[(size_t)col * 16 + c];
    asm volatile("red.global.add.noftz.v2.f16x2 [%0], {%1, %2};"
                 :: "l"(pd), "r"(u0), "r"(u1)
                 : "memory");
}

// final: out = (x + y + z) / 3,  y = out (fp32 accum), z = fp16 accum.
__global__ void k_final(const float4* __restrict__ x, float4* __restrict__ out,
                        int n4) {
    int i = blockIdx.x * blockDim.x + threadIdx.x;
    if (i >= n4) return;
    float4 yv = out[i];
    float4 a  = __ldg(&x[i]);
    float4 z  = h4_to_f4(g_h[i]);
    const float s = 1.0f / 3.0f;
    out[i] = make_float4((a.x + yv.x + z.x) * s, (a.y + yv.y + z.y) * s,
                         (a.z + yv.z + z.z) * s, (a.w + yv.w + z.w) * s);
}

// ---------------------------------------------------------------------------
extern "C" void kernel_launch(void* const* d_in, const int* in_sizes, int n_in,
                              void* d_out, int out_size) {
    // Input-order detection: x has N*64 = 9.6M elements; edge_index has
    // 2E = 4M elements. x is strictly larger.
    int ix = 0, ie = 1;
    if (n_in >= 2 && in_sizes[0] < in_sizes[1]) { ix = 1; ie = 0; }

    const float4* x   = (const float4*)d_in[ix];
    const int*    e32 = (const int*)d_in[ie];
    float4*       out = (float4*)d_out;

    int N = in_sizes[ix] / 64;
    int E = in_sizes[ie] / 2;
    if (N > MAXN) N = MAXN;

    const int TB = 256;
    const int n4 = N * 16;
    const int gO = (n4 + TB - 1) / TB;
    const int gN = (N + TB - 1) / TB;
    const int gE1 = (E + TB - 1) / TB;
    const long long workE = (long long)E * 16;
    const int gE16 = (int)((workE + TB - 1) / TB);

    // dtype detect (reads <=8KB — in bounds under both interpretations)
    {
        int npairs = E;
        if (npairs > 1024) npairs = 1024;
        k_detect<<<1, 256>>>((const int2*)e32, npairs);
    }

    // zero out + z-accumulator + deg in one pass
    k_zero<<<gO, TB>>>(out, n4, N);

    // degrees + normalization coefficients
    k_deg<<<gE1, TB>>>(e32, E, N);
    k_dis<<<gN, TB>>>(N);

    // y = A'x accumulated in fp32 directly in out
    k_conv1<<<gE16, TB>>>(x, out, e32, E, N);

    // z = A'y accumulated in fp16 (half the scatter-RMW bytes)
    k_conv2<<<gE16, TB>>>(out, e32, E, N);

    // out = (x + y + z) / 3
    k_final<<<gO, TB>>>(x, out, n4);
}

// round 14
// speedup vs baseline: 1.3440x; 1.2117x over previous
#include <cuda_runtime.h>
#include <cuda_fp16.h>
#include <cstdint>

// ---------------------------------------------------------------------------
// LightGCN forward: out = (x + A'x + A'(A'x)) / 3
// per-edge norm (row->col): dis[row]*dis[col], dis = rsqrt(indeg) or 0.
// N = 150000, D = 64 fp32, E = 2,000,000 ([2,E], int64 OR int32, runtime-
// detected).
// Round-13 finding: convs are bound by L2 reduction OP RATE (~1 op/slice/cyc),
// not bytes. So: counting-sort edges by destination, then edge-parallel conv
// over fixed 16-edge chunks with register accumulation — REDG only on column
// boundaries (~2.2 flushes/chunk) => ~7x fewer reduction ops.
// conv2 in two half-width passes into a 9.6MB fp16 z accumulator; total
// scratch ~19.4MB (proven-safe; 39.6MB trips the harness mem check).
// ---------------------------------------------------------------------------

#define MAXN 150016
#define MAXE 2000000
#define SCAN_B 1024
#define NBLK_MAX ((MAXN + SCAN_B - 1) / SCAN_B)
#define CHUNK 16

// Scratch: ~19.4 MB total.
__device__ int   g_shift;                // 1 if edge dtype int64, 0 if int32
__device__ int   g_degi[MAXN];           // in-degree
__device__ int   g_cur[MAXN];            // excl offsets -> END offsets after sort
__device__ float g_dis[MAXN];
__device__ int   g_srow[MAXE];           // source row per edge, sorted by col (8MB)
__device__ uint2 g_zh[MAXN * 8];         // fp16x4 half-width z accumulator (9.6MB)
__device__ int   g_bsum[NBLK_MAX];

// ---------------------------------------------------------------------------
__global__ void k_detect(const int2* __restrict__ p, int npairs) {
    __shared__ int nz;
    if (threadIdx.x == 0) nz = 0;
    __syncthreads();
    int local = 0;
    for (int i = threadIdx.x; i < npairs; i += blockDim.x)
        if (p[i].y != 0) local = 1;
    if (local) atomicOr(&nz, 1);
    __syncthreads();
    if (threadIdx.x == 0) g_shift = (nz == 0) ? 1 : 0;
}

__device__ __forceinline__ unsigned load_idx(const int* __restrict__ p32,
                                             long long pos, int shift) {
    return (unsigned)p32[pos << shift];
}

// Zero out (38.4MB), z accumulator (9.6MB), degi. Grid covers n4 = N*16.
__global__ void k_zero(float4* __restrict__ out, int n4, int N) {
    int i = blockIdx.x * blockDim.x + threadIdx.x;
    if (i < N) g_degi[i] = 0;
    if (i < n4) {
        out[i] = make_float4(0.f, 0.f, 0.f, 0.f);
        if (i < (n4 >> 1)) g_zh[i] = make_uint2(0u, 0u);
    }
}

__global__ void k_hist(const int* __restrict__ e32, int E, int N) {
    int i = blockIdx.x * blockDim.x + threadIdx.x;
    if (i >= E) return;
    int sh = g_shift;
    unsigned col = load_idx(e32, (long long)E + i, sh);
    if (col < (unsigned)N) atomicAdd(&g_degi[col], 1);
}

__global__ void k_scan1(int N) {
    __shared__ int sh[SCAN_B];
    int tid = threadIdx.x;
    int gid = blockIdx.x * SCAN_B + tid;
    int v = (gid < N) ? g_degi[gid] : 0;
    sh[tid] = v;
    __syncthreads();
    for (int off = 1; off < SCAN_B; off <<= 1) {
        int t = (tid >= off) ? sh[tid - off] : 0;
        __syncthreads();
        sh[tid] += t;
        __syncthreads();
    }
    if (gid < N) g_cur[gid] = sh[tid] - v;  // exclusive within block
    if (tid == SCAN_B - 1) g_bsum[blockIdx.x] = sh[tid];
}

__global__ void k_scan2(int nb) {
    if (threadIdx.x == 0) {
        int run = 0;
        for (int i = 0; i < nb; ++i) { int t = g_bsum[i]; g_bsum[i] = run; run += t; }
    }
}

__global__ void k_scan3(int N) {
    int gid = blockIdx.x * blockDim.x + threadIdx.x;
    if (gid < N) g_cur[gid] += g_bsum[gid / SCAN_B];
}

// Counting-sort scatter; afterwards g_cur[col] == END offset of col's run.
__global__ void k_sort(const int* __restrict__ e32, int E, int N) {
    int i = blockIdx.x * blockDim.x + threadIdx.x;
    if (i >= E) return;
    int sh = g_shift;
    unsigned row = load_idx(e32, i, sh);
    unsigned col = load_idx(e32, (long long)E + i, sh);
    if (row >= (unsigned)N || col >= (unsigned)N) return;
    int pos = atomicAdd(&g_cur[col], 1);
    g_srow[pos] = (int)row;
}

__global__ void k_dis(int N) {
    int i = blockIdx.x * blockDim.x + threadIdx.x;
    if (i >= N) return;
    int d = g_degi[i];
    g_dis[i] = (d > 0) ? rsqrtf((float)d) : 0.0f;
}

// Smallest col with end[col] > j (cur is non-decreasing end offsets).
__device__ __forceinline__ int find_col(int N, int j) {
    int lo = 0, hi = N - 1;
    while (lo < hi) {
        int mid = (lo + hi) >> 1;
        if (g_cur[mid] > j) hi = mid; else lo = mid + 1;
    }
    return lo;
}

// conv1: out[col] += dis[col] * sum(dis[row]*x[row]) over sorted runs.
// 16 lanes per 16-edge chunk; register accumulation; v4-REDG only at column
// boundaries (~2.2 per chunk). Gathers are 256B coalesced per edge.
__global__ void __launch_bounds__(256) k_conv1(
        const float4* __restrict__ x, float4* __restrict__ out, int E, int N) {
    int t = blockIdx.x * blockDim.x + threadIdx.x;
    int chunk = t >> 4, c = t & 15;
    int total = g_cur[N - 1];
    int s = chunk * CHUNK;
    if (s >= total) return;
    int e = s + CHUNK; if (e > total) e = total;

    int col = find_col(N, s);
    int bound = g_cur[col];
    float4 acc = make_float4(0.f, 0.f, 0.f, 0.f);

    for (int j = s; j < e; ++j) {
        if (j >= bound) {
            float dc = g_dis[col];
            float4* pd = &out[(size_t)col * 16 + c];
            asm volatile("red.global.add.v4.f32 [%0], {%1, %2, %3, %4};"
                         :: "l"(pd), "f"(acc.x * dc), "f"(acc.y * dc),
                            "f"(acc.z * dc), "f"(acc.w * dc) : "memory");
            acc = make_float4(0.f, 0.f, 0.f, 0.f);
            do { ++col; bound = g_cur[col]; } while (bound <= j);
        }
        int row = g_srow[j];
        float w = __ldg(&g_dis[row]);
        float4 v = __ldg(&x[(size_t)row * 16 + c]);
        acc.x += w * v.x; acc.y += w * v.y; acc.z += w * v.z; acc.w += w * v.w;
    }
    float dc = g_dis[col];
    float4* pd = &out[(size_t)col * 16 + c];
    asm volatile("red.global.add.v4.f32 [%0], {%1, %2, %3, %4};"
                 :: "l"(pd), "f"(acc.x * dc), "f"(acc.y * dc),
                    "f"(acc.z * dc), "f"(acc.w * dc) : "memory");
}

// conv2 (half-width pass): z[col] += fp16(dis[col]*sum(dis[row]*y[row])),
// 8 lanes per chunk, y gathered fp32 from out (dims xoff*4..xoff*4+31).
__global__ void __launch_bounds__(256) k_conv2(
        const float4* __restrict__ y, int E, int N, int xoff) {
    int t = blockIdx.x * blockDim.x + threadIdx.x;
    int chunk = t >> 3, c = t & 7;
    int total = g_cur[N - 1];
    int s = chunk * CHUNK;
    if (s >= total) return;
    int e = s + CHUNK; if (e > total) e = total;

    int col = find_col(N, s);
    int bound = g_cur[col];
    float4 acc = make_float4(0.f, 0.f, 0.f, 0.f);

    for (int j = s; j < e; ++j) {
        if (j >= bound) {
            float dc = g_dis[col];
            __half2 h0 = __floats2half2_rn(acc.x * dc, acc.y * dc);
            __half2 h1 = __floats2half2_rn(acc.z * dc, acc.w * dc);
            uint2* pd = &g_zh[(size_t)col * 8 + c];
            asm volatile("red.global.add.noftz.v2.f16x2 [%0], {%1, %2};"
                         :: "l"(pd), "r"(*(const unsigned*)&h0),
                            "r"(*(const unsigned*)&h1) : "memory");
            acc = make_float4(0.f, 0.f, 0.f, 0.f);
            do { ++col; bound = g_cur[col]; } while (bound <= j);
        }
        int row = g_srow[j];
        float w = __ldg(&g_dis[row]);
        float4 v = __ldg(&y[(size_t)row * 16 + xoff + c]);
        acc.x += w * v.x; acc.y += w * v.y; acc.z += w * v.z; acc.w += w * v.w;
    }
    float dc = g_dis[col];
    __half2 h0 = __floats2half2_rn(acc.x * dc, acc.y * dc);
    __half2 h1 = __floats2half2_rn(acc.z * dc, acc.w * dc);
    uint2* pd = &g_zh[(size_t)col * 8 + c];
    asm volatile("red.global.add.noftz.v2.f16x2 [%0], {%1, %2};"
                 :: "l"(pd), "r"(*(const unsigned*)&h0),
                    "r"(*(const unsigned*)&h1) : "memory");
}

// final (half-width): out = (x + y + z)/3 on dims [xoff*4, xoff*4+32);
// also re-zero z for the next half pass.
__global__ void k_final(const float4* __restrict__ x, float4* __restrict__ out,
                        int nh, int xoff) {  // nh = N*8
    int i = blockIdx.x * blockDim.x + threadIdx.x;
    if (i >= nh) return;
    int node = i >> 3, cc = i & 7;
    size_t oidx = (size_t)node * 16 + xoff + cc;
    float4 yv = out[oidx];
    float4 a  = __ldg(&x[oidx]);
    uint2  zh = g_zh[i];
    g_zh[i] = make_uint2(0u, 0u);
    float2 z0 = __half22float2(*(const __half2*)&zh.x);
    float2 z1 = __half22float2(*(const __half2*)&zh.y);
    const float s = 1.0f / 3.0f;
    out[oidx] = make_float4((a.x + yv.x + z0.x) * s, (a.y + yv.y + z0.y) * s,
                            (a.z + yv.z + z1.x) * s, (a.w + yv.w + z1.y) * s);
}

// ---------------------------------------------------------------------------
extern "C" void kernel_launch(void* const* d_in, const int* in_sizes, int n_in,
                              void* d_out, int out_size) {
    int ix = 0, ie = 1;
    if (n_in >= 2 && in_sizes[0] < in_sizes[1]) { ix = 1; ie = 0; }

    const float4* x   = (const float4*)d_in[ix];
    const int*    e32 = (const int*)d_in[ie];
    float4*       out = (float4*)d_out;

    int N = in_sizes[ix] / 64;
    int E = in_sizes[ie] / 2;
    if (N > MAXN) N = MAXN;
    if (E > MAXE) E = MAXE;

    const int TB = 256;
    const int n4 = N * 16;
    const int nh = N * 8;
    const int gO = (n4 + TB - 1) / TB;
    const int gN = (N + TB - 1) / TB;
    const int gE = (E + TB - 1) / TB;
    const int gH = (nh + TB - 1) / TB;
    const int nb = (N + SCAN_B - 1) / SCAN_B;
    const int nchunk = (E + CHUNK - 1) / CHUNK;
    const int gC16 = (nchunk * 16 + TB - 1) / TB;
    const int gC8  = (nchunk * 8 + TB - 1) / TB;

    // dtype detect (reads <=8KB — in bounds under both interpretations)
    {
        int npairs = E;
        if (npairs > 1024) npairs = 1024;
        k_detect<<<1, 256>>>((const int2*)e32, npairs);
    }

    // zero out + z + degi; CSR build: hist -> scan -> sort; dis
    k_zero<<<gO, TB>>>(out, n4, N);
    k_hist<<<gE, TB>>>(e32, E, N);
    k_scan1<<<nb, SCAN_B>>>(N);
    k_scan2<<<1, 32>>>(nb);
    k_scan3<<<gN, TB>>>(N);
    k_sort<<<gE, TB>>>(e32, E, N);
    k_dis<<<gN, TB>>>(N);

    // y = A'x accumulated fp32 in out (segmented scatter, ~7x fewer REDGs)
    k_conv1<<<gC16, TB>>>(x, out, E, N);

    // two half-width passes: z = A'y (fp16 accum), then fuse epilogue
    k_conv2<<<gC8, TB>>>(out, E, N, 0);
    k_final<<<gH, TB>>>(x, out, nh, 0);
    k_conv2<<<gC8, TB>>>(out, E, N, 8);
    k_final<<<gH, TB>>>(x, out, nh, 8);
}

// round 15
// speedup vs baseline: 1.4016x; 1.0429x over previous
#include <cuda_runtime.h>
#include <cuda_fp16.h>
#include <cstdint>

// ---------------------------------------------------------------------------
// LightGCN forward: out = (x + A'x + A'(A'x)) / 3
// per-edge norm (row->col): dis[row]*dis[col], dis = rsqrt(indeg) or 0.
// N = 150000, D = 64 fp32, E = 2,000,000 ([2,E], int64 OR int32, runtime-
// detected).
// Architecture (R14-proven): counting-sort edges by destination; conv runs
// edge-parallel over fixed 32-edge chunks with register accumulation and
// REDG flushes only at column boundaries (~3.5 per chunk). conv2 in two
// half-width passes into a 9.6MB fp16 z accumulator.
// Scratch ~19.4MB (proven-safe; 39.6MB trips the harness mem check).
// ---------------------------------------------------------------------------

#define MAXN 150016
#define MAXE 2000000
#define SCAN_B 1024
#define NBLK_MAX ((MAXN + SCAN_B - 1) / SCAN_B)
#define CHUNK 32

// Scratch: ~19.4 MB total.
__device__ int   g_shift;                // 1 if edge dtype int64, 0 if int32
__device__ int   g_degi[MAXN];           // in-degree
__device__ int   g_cur[MAXN];            // excl offsets -> END offsets after sort
__device__ float g_dis[MAXN];
__device__ int   g_srow[MAXE];           // source row per edge, sorted by col (8MB)
__device__ uint2 g_zh[MAXN * 8];         // fp16x4 half-width z accumulator (9.6MB)
__device__ int   g_bsum[NBLK_MAX];

// ---------------------------------------------------------------------------
__global__ void k_detect(const int2* __restrict__ p, int npairs) {
    __shared__ int nz;
    if (threadIdx.x == 0) nz = 0;
    __syncthreads();
    int local = 0;
    for (int i = threadIdx.x; i < npairs; i += blockDim.x)
        if (p[i].y != 0) local = 1;
    if (local) atomicOr(&nz, 1);
    __syncthreads();
    if (threadIdx.x == 0) g_shift = (nz == 0) ? 1 : 0;
}

__device__ __forceinline__ unsigned load_idx(const int* __restrict__ p32,
                                             long long pos, int shift) {
    return (unsigned)p32[pos << shift];
}

// Zero out (38.4MB), z accumulator (9.6MB), degi. Grid covers n4 = N*16.
__global__ void k_zero(float4* __restrict__ out, int n4, int N) {
    int i = blockIdx.x * blockDim.x + threadIdx.x;
    if (i < N) g_degi[i] = 0;
    if (i < n4) {
        out[i] = make_float4(0.f, 0.f, 0.f, 0.f);
        if (i < (n4 >> 1)) g_zh[i] = make_uint2(0u, 0u);
    }
}

__global__ void k_hist(const int* __restrict__ e32, int E, int N) {
    int i = blockIdx.x * blockDim.x + threadIdx.x;
    if (i >= E) return;
    int sh = g_shift;
    unsigned col = load_idx(e32, (long long)E + i, sh);
    if (col < (unsigned)N) atomicAdd(&g_degi[col], 1);
}

__global__ void k_scan1(int N) {
    __shared__ int sh[SCAN_B];
    int tid = threadIdx.x;
    int gid = blockIdx.x * SCAN_B + tid;
    int v = (gid < N) ? g_degi[gid] : 0;
    sh[tid] = v;
    __syncthreads();
    for (int off = 1; off < SCAN_B; off <<= 1) {
        int t = (tid >= off) ? sh[tid - off] : 0;
        __syncthreads();
        sh[tid] += t;
        __syncthreads();
    }
    if (gid < N) g_cur[gid] = sh[tid] - v;  // exclusive within block
    if (tid == SCAN_B - 1) g_bsum[blockIdx.x] = sh[tid];
}

__global__ void k_scan2(int nb) {
    if (threadIdx.x == 0) {
        int run = 0;
        for (int i = 0; i < nb; ++i) { int t = g_bsum[i]; g_bsum[i] = run; run += t; }
    }
}

// scan3 + dis fused (dis needs only degi).
__global__ void k_scan3(int N) {
    int gid = blockIdx.x * blockDim.x + threadIdx.x;
    if (gid >= N) return;
    g_cur[gid] += g_bsum[gid / SCAN_B];
    int d = g_degi[gid];
    g_dis[gid] = (d > 0) ? rsqrtf((float)d) : 0.0f;
}

// Counting-sort scatter; afterwards g_cur[col] == END offset of col's run.
__global__ void k_sort(const int* __restrict__ e32, int E, int N) {
    int i = blockIdx.x * blockDim.x + threadIdx.x;
    if (i >= E) return;
    int sh = g_shift;
    unsigned row = load_idx(e32, i, sh);
    unsigned col = load_idx(e32, (long long)E + i, sh);
    if (row >= (unsigned)N || col >= (unsigned)N) return;
    int pos = atomicAdd(&g_cur[col], 1);
    g_srow[pos] = (int)row;
}

// Smallest col with end[col] > j (cur is non-decreasing end offsets).
__device__ __forceinline__ int find_col(int N, int j) {
    int lo = 0, hi = N - 1;
    while (lo < hi) {
        int mid = (lo + hi) >> 1;
        if (g_cur[mid] > j) hi = mid; else lo = mid + 1;
    }
    return lo;
}

// conv1: out[col] += dis[col] * sum(dis[row]*x[row]) over sorted runs.
// 16 lanes per 32-edge chunk; run-structured inner loop (branch-free gather
// body); v4-REDG only at run boundaries. Gathers 256B coalesced per edge.
__global__ void __launch_bounds__(256) k_conv1(
        const float4* __restrict__ x, float4* __restrict__ out, int E, int N) {
    int t = blockIdx.x * blockDim.x + threadIdx.x;
    int chunk = t >> 4, c = t & 15;
    int total = g_cur[N - 1];
    int s = chunk * CHUNK;
    if (s >= total) return;
    int e = s + CHUNK; if (e > total) e = total;

    int col = find_col(N, s);
    int bound = g_cur[col];
    int j = s;
    while (true) {
        int runend = bound < e ? bound : e;
        float4 acc = make_float4(0.f, 0.f, 0.f, 0.f);
        for (; j < runend; ++j) {
            int row = g_srow[j];
            float w = __ldg(&g_dis[row]);
            float4 v = __ldg(&x[(size_t)row * 16 + c]);
            acc.x += w * v.x; acc.y += w * v.y;
            acc.z += w * v.z; acc.w += w * v.w;
        }
        float dc = g_dis[col];
        float4* pd = &out[(size_t)col * 16 + c];
        asm volatile("red.global.add.v4.f32 [%0], {%1, %2, %3, %4};"
                     :: "l"(pd), "f"(acc.x * dc), "f"(acc.y * dc),
                        "f"(acc.z * dc), "f"(acc.w * dc) : "memory");
        if (j >= e) break;
        do { ++col; bound = g_cur[col]; } while (bound <= j);
    }
}

// conv2 (half-width): z[col] += fp16(dis[col]*sum(dis[row]*y[row])),
// 8 lanes per 32-edge chunk; y gathered fp32 from out.
__global__ void __launch_bounds__(256) k_conv2(
        const float4* __restrict__ y, int E, int N, int xoff) {
    int t = blockIdx.x * blockDim.x + threadIdx.x;
    int chunk = t >> 3, c = t & 7;
    int total = g_cur[N - 1];
    int s = chunk * CHUNK;
    if (s >= total) return;
    int e = s + CHUNK; if (e > total) e = total;

    int col = find_col(N, s);
    int bound = g_cur[col];
    int j = s;
    while (true) {
        int runend = bound < e ? bound : e;
        float4 acc = make_float4(0.f, 0.f, 0.f, 0.f);
        for (; j < runend; ++j) {
            int row = g_srow[j];
            float w = __ldg(&g_dis[row]);
            float4 v = __ldg(&y[(size_t)row * 16 + xoff + c]);
            acc.x += w * v.x; acc.y += w * v.y;
            acc.z += w * v.z; acc.w += w * v.w;
        }
        float dc = g_dis[col];
        __half2 h0 = __floats2half2_rn(acc.x * dc, acc.y * dc);
        __half2 h1 = __floats2half2_rn(acc.z * dc, acc.w * dc);
        uint2* pd = &g_zh[(size_t)col * 8 + c];
        asm volatile("red.global.add.noftz.v2.f16x2 [%0], {%1, %2};"
                     :: "l"(pd), "r"(*(const unsigned*)&h0),
                        "r"(*(const unsigned*)&h1) : "memory");
        if (j >= e) break;
        do { ++col; bound = g_cur[col]; } while (bound <= j);
    }
}

// final (half-width): out = (x + y + z)/3 on 32 dims starting at xoff*4;
// re-zeros z for the next half pass.
__global__ void k_final(const float4* __restrict__ x, float4* __restrict__ out,
                        int nh, int xoff) {  // nh = N*8
    int i = blockIdx.x * blockDim.x + threadIdx.x;
    if (i >= nh) return;
    int node = i >> 3, cc = i & 7;
    size_t oidx = (size_t)node * 16 + xoff + cc;
    float4 yv = out[oidx];
    float4 a  = __ldg(&x[oidx]);
    uint2  zh = g_zh[i];
    g_zh[i] = make_uint2(0u, 0u);
    float2 z0 = __half22float2(*(const __half2*)&zh.x);
    float2 z1 = __half22float2(*(const __half2*)&zh.y);
    const float s = 1.0f / 3.0f;
    out[oidx] = make_float4((a.x + yv.x + z0.x) * s, (a.y + yv.y + z0.y) * s,
                            (a.z + yv.z + z1.x) * s, (a.w + yv.w + z1.y) * s);
}

// ---------------------------------------------------------------------------
extern "C" void kernel_launch(void* const* d_in, const int* in_sizes, int n_in,
                              void* d_out, int out_size) {
    int ix = 0, ie = 1;
    if (n_in >= 2 && in_sizes[0] < in_sizes[1]) { ix = 1; ie = 0; }

    const float4* x   = (const float4*)d_in[ix];
    const int*    e32 = (const int*)d_in[ie];
    float4*       out = (float4*)d_out;

    int N = in_sizes[ix] / 64;
    int E = in_sizes[ie] / 2;
    if (N > MAXN) N = MAXN;
    if (E > MAXE) E = MAXE;

    const int TB = 256;
    const int n4 = N * 16;
    const int nh = N * 8;
    const int gO = (n4 + TB - 1) / TB;
    const int gN = (N + TB - 1) / TB;
    const int gE = (E + TB - 1) / TB;
    const int gH = (nh + TB - 1) / TB;
    const int nb = (N + SCAN_B - 1) / SCAN_B;
    const int nchunk = (E + CHUNK - 1) / CHUNK;
    const int gC16 = (nchunk * 16 + TB - 1) / TB;
    const int gC8  = (nchunk * 8 + TB - 1) / TB;

    // dtype detect (reads <=8KB — in bounds under both interpretations)
    {
        int npairs = E;
        if (npairs > 1024) npairs = 1024;
        k_detect<<<1, 256>>>((const int2*)e32, npairs);
    }

    // zero out + z + degi; CSR build: hist -> scan(+dis) -> sort
    k_zero<<<gO, TB>>>(out, n4, N);
    k_hist<<<gE, TB>>>(e32, E, N);
    k_scan1<<<nb, SCAN_B>>>(N);
    k_scan2<<<1, 32>>>(nb);
    k_scan3<<<gN, TB>>>(N);
    k_sort<<<gE, TB>>>(e32, E, N);

    // y = A'x accumulated fp32 in out (segmented scatter)
    k_conv1<<<gC16, TB>>>(x, out, E, N);

    // two half-width passes: z = A'y (fp16 accum), then fused epilogue
    k_conv2<<<gC8, TB>>>(out, E, N, 0);
    k_final<<<gH, TB>>>(x, out, nh, 0);
    k_conv2<<<gC8, TB>>>(out, E, N, 8);
    k_final<<<gH, TB>>>(x, out, nh, 8);
}

// round 16
// speedup vs baseline: 1.5182x; 1.0832x over previous
#include <cuda_runtime.h>
#include <cuda_fp16.h>
#include <cstdint>

// ---------------------------------------------------------------------------
// LightGCN forward: out = (x + A'x + A'(A'x)) / 3
// per-edge norm (row->col): dis[row]*dis[col], dis = rsqrt(indeg) or 0.
// N = 150000, D = 64 fp32, E = 2,000,000 ([2,E], int64 OR int32, runtime-
// detected).
// Architecture (R14/15-proven): counting-sort edges by destination; conv runs
// edge-parallel over fixed 64-edge chunks with register accumulation and
// REDG flushes only at column boundaries. conv2 in two half-width passes into
// a 9.6MB fp16 z accumulator. Warp-shuffle scans for the CSR build.
// Scratch ~19.4MB (proven-safe; 39.6MB trips the harness mem check).
// ---------------------------------------------------------------------------

#define MAXN 150016
#define MAXE 2000000
#define SCAN_B 1024
#define NBLK_MAX ((MAXN + SCAN_B - 1) / SCAN_B)
#define CHUNK 64

// Scratch: ~19.4 MB total.
__device__ int   g_shift;                // 1 if edge dtype int64, 0 if int32
__device__ int   g_degi[MAXN];           // in-degree
__device__ int   g_cur[MAXN];            // excl offsets -> END offsets after sort
__device__ float g_dis[MAXN];
__device__ int   g_srow[MAXE];           // source row per edge, sorted by col (8MB)
__device__ uint2 g_zh[MAXN * 8];         // fp16x4 half-width z accumulator (9.6MB)
__device__ int   g_bsum[NBLK_MAX];

// ---------------------------------------------------------------------------
__global__ void k_detect(const int2* __restrict__ p, int npairs) {
    __shared__ int nz;
    if (threadIdx.x == 0) nz = 0;
    __syncthreads();
    int local = 0;
    for (int i = threadIdx.x; i < npairs; i += blockDim.x)
        if (p[i].y != 0) local = 1;
    if (local) atomicOr(&nz, 1);
    __syncthreads();
    if (threadIdx.x == 0) g_shift = (nz == 0) ? 1 : 0;
}

__device__ __forceinline__ unsigned load_idx(const int* __restrict__ p32,
                                             long long pos, int shift) {
    return (unsigned)p32[pos << shift];
}

// Zero out (38.4MB), z accumulator (9.6MB), degi. Grid covers n4 = N*16.
__global__ void k_zero(float4* __restrict__ out, int n4, int N) {
    int i = blockIdx.x * blockDim.x + threadIdx.x;
    if (i < N) g_degi[i] = 0;
    if (i < n4) {
        out[i] = make_float4(0.f, 0.f, 0.f, 0.f);
        if (i < (n4 >> 1)) g_zh[i] = make_uint2(0u, 0u);
    }
}

__global__ void k_hist(const int* __restrict__ e32, int E, int N) {
    int i = blockIdx.x * blockDim.x + threadIdx.x;
    if (i >= E) return;
    int sh = g_shift;
    unsigned col = load_idx(e32, (long long)E + i, sh);
    if (col < (unsigned)N) atomicAdd(&g_degi[col], 1);
}

// Block-level exclusive scan via warp shuffles (2 barriers, not 20).
__global__ void k_scan1(int N) {
    __shared__ int warp_tot[SCAN_B / 32];
    int tid = threadIdx.x;
    int gid = blockIdx.x * SCAN_B + tid;
    int lane = tid & 31, wid = tid >> 5;
    int v = (gid < N) ? g_degi[gid] : 0;

    // inclusive warp scan
    int s = v;
    #pragma unroll
    for (int off = 1; off < 32; off <<= 1) {
        int t = __shfl_up_sync(0xffffffffu, s, off);
        if (lane >= off) s += t;
    }
    if (lane == 31) warp_tot[wid] = s;
    __syncthreads();

    // warp 0 scans the 32 warp totals (exclusive)
    if (wid == 0) {
        int w = warp_tot[lane];
        int ws = w;
        #pragma unroll
        for (int off = 1; off < 32; off <<= 1) {
            int t = __shfl_up_sync(0xffffffffu, ws, off);
            if (lane >= off) ws += t;
        }
        warp_tot[lane] = ws - w;  // exclusive
    }
    __syncthreads();

    int incl = s + warp_tot[wid];
    if (gid < N) g_cur[gid] = incl - v;  // exclusive within block
    if (tid == SCAN_B - 1) g_bsum[blockIdx.x] = incl;
}

// One warp scans up to NBLK_MAX block sums (shuffle scan in 32-chunks).
__global__ void k_scan2(int nb) {
    int lane = threadIdx.x;
    int run = 0;
    for (int base = 0; base < nb; base += 32) {
        int i = base + lane;
        int v = (i < nb) ? g_bsum[i] : 0;
        int s = v;
        #pragma unroll
        for (int off = 1; off < 32; off <<= 1) {
            int t = __shfl_up_sync(0xffffffffu, s, off);
            if (lane >= off) s += t;
        }
        if (i < nb) g_bsum[i] = run + s - v;  // exclusive
        run += __shfl_sync(0xffffffffu, s, 31);
    }
}

// scan3 + dis fused (dis needs only degi).
__global__ void k_scan3(int N) {
    int gid = blockIdx.x * blockDim.x + threadIdx.x;
    if (gid >= N) return;
    g_cur[gid] += g_bsum[gid / SCAN_B];
    int d = g_degi[gid];
    g_dis[gid] = (d > 0) ? rsqrtf((float)d) : 0.0f;
}

// Counting-sort scatter; afterwards g_cur[col] == END offset of col's run.
__global__ void k_sort(const int* __restrict__ e32, int E, int N) {
    int i = blockIdx.x * blockDim.x + threadIdx.x;
    if (i >= E) return;
    int sh = g_shift;
    unsigned row = load_idx(e32, i, sh);
    unsigned col = load_idx(e32, (long long)E + i, sh);
    if (row >= (unsigned)N || col >= (unsigned)N) return;
    int pos = atomicAdd(&g_cur[col], 1);
    g_srow[pos] = (int)row;
}

// Smallest col with end[col] > j (cur is non-decreasing end offsets).
__device__ __forceinline__ int find_col(int N, int j) {
    int lo = 0, hi = N - 1;
    while (lo < hi) {
        int mid = (lo + hi) >> 1;
        if (g_cur[mid] > j) hi = mid; else lo = mid + 1;
    }
    return lo;
}

// conv1: out[col] += dis[col] * sum(dis[row]*x[row]) over sorted runs.
// 16 lanes per 64-edge chunk; run-structured inner loop; v4-REDG only at
// run boundaries. Gathers 256B coalesced per edge.
__global__ void __launch_bounds__(256) k_conv1(
        const float4* __restrict__ x, float4* __restrict__ out, int E, int N) {
    int t = blockIdx.x * blockDim.x + threadIdx.x;
    int chunk = t >> 4, c = t & 15;
    int total = g_cur[N - 1];
    int s = chunk * CHUNK;
    if (s >= total) return;
    int e = s + CHUNK; if (e > total) e = total;

    int col = find_col(N, s);
    int bound = g_cur[col];
    int j = s;
    while (true) {
        int runend = bound < e ? bound : e;
        float4 acc = make_float4(0.f, 0.f, 0.f, 0.f);
        for (; j < runend; ++j) {
            int row = g_srow[j];
            float w = __ldg(&g_dis[row]);
            float4 v = __ldg(&x[(size_t)row * 16 + c]);
            acc.x += w * v.x; acc.y += w * v.y;
            acc.z += w * v.z; acc.w += w * v.w;
        }
        float dc = g_dis[col];
        float4* pd = &out[(size_t)col * 16 + c];
        asm volatile("red.global.add.v4.f32 [%0], {%1, %2, %3, %4};"
                     :: "l"(pd), "f"(acc.x * dc), "f"(acc.y * dc),
                        "f"(acc.z * dc), "f"(acc.w * dc) : "memory");
        if (j >= e) break;
        do { ++col; bound = g_cur[col]; } while (bound <= j);
    }
}

// conv2 (half-width): z[col] += fp16(dis[col]*sum(dis[row]*y[row])),
// 8 lanes per 64-edge chunk; y gathered fp32 from out.
__global__ void __launch_bounds__(256) k_conv2(
        const float4* __restrict__ y, int E, int N, int xoff) {
    int t = blockIdx.x * blockDim.x + threadIdx.x;
    int chunk = t >> 3, c = t & 7;
    int total = g_cur[N - 1];
    int s = chunk * CHUNK;
    if (s >= total) return;
    int e = s + CHUNK; if (e > total) e = total;

    int col = find_col(N, s);
    int bound = g_cur[col];
    int j = s;
    while (true) {
        int runend = bound < e ? bound : e;
        float4 acc = make_float4(0.f, 0.f, 0.f, 0.f);
        for (; j < runend; ++j) {
            int row = g_srow[j];
            float w = __ldg(&g_dis[row]);
            float4 v = __ldg(&y[(size_t)row * 16 + xoff + c]);
            acc.x += w * v.x; acc.y += w * v.y;
            acc.z += w * v.z; acc.w += w * v.w;
        }
        float dc = g_dis[col];
        __half2 h0 = __floats2half2_rn(acc.x * dc, acc.y * dc);
        __half2 h1 = __floats2half2_rn(acc.z * dc, acc.w * dc);
        uint2* pd = &g_zh[(size_t)col * 8 + c];
        asm volatile("red.global.add.noftz.v2.f16x2 [%0], {%1, %2};"
                     :: "l"(pd), "r"(*(const unsigned*)&h0),
                        "r"(*(const unsigned*)&h1) : "memory");
        if (j >= e) break;
        do { ++col; bound = g_cur[col]; } while (bound <= j);
    }
}

// final (half-width): out = (x + y + z)/3 on 32 dims starting at xoff*4;
// re-zeros z for the next half pass.
__global__ void k_final(const float4* __restrict__ x, float4* __restrict__ out,
                        int nh, int xoff) {  // nh = N*8
    int i = blockIdx.x * blockDim.x + threadIdx.x;
    if (i >= nh) return;
    int node = i >> 3, cc = i & 7;
    size_t oidx = (size_t)node * 16 + xoff + cc;
    float4 yv = out[oidx];
    float4 a  = __ldg(&x[oidx]);
    uint2  zh = g_zh[i];
    g_zh[i] = make_uint2(0u, 0u);
    float2 z0 = __half22float2(*(const __half2*)&zh.x);
    float2 z1 = __half22float2(*(const __half2*)&zh.y);
    const float s = 1.0f / 3.0f;
    out[oidx] = make_float4((a.x + yv.x + z0.x) * s, (a.y + yv.y + z0.y) * s,
                            (a.z + yv.z + z1.x) * s, (a.w + yv.w + z1.y) * s);
}

// ---------------------------------------------------------------------------
extern "C" void kernel_launch(void* const* d_in, const int* in_sizes, int n_in,
                              void* d_out, int out_size) {
    int ix = 0, ie = 1;
    if (n_in >= 2 && in_sizes[0] < in_sizes[1]) { ix = 1; ie = 0; }

    const float4* x   = (const float4*)d_in[ix];
    const int*    e32 = (const int*)d_in[ie];
    float4*       out = (float4*)d_out;

    int N = in_sizes[ix] / 64;
    int E = in_sizes[ie] / 2;
    if (N > MAXN) N = MAXN;
    if (E > MAXE) E = MAXE;

    const int TB = 256;
    const int n4 = N * 16;
    const int nh = N * 8;
    const int gO = (n4 + TB - 1) / TB;
    const int gN = (N + TB - 1) / TB;
    const int gE = (E + TB - 1) / TB;
    const int gH = (nh + TB - 1) / TB;
    const int nb = (N + SCAN_B - 1) / SCAN_B;
    const int nchunk = (E + CHUNK - 1) / CHUNK;
    const int gC16 = (nchunk * 16 + TB - 1) / TB;
    const int gC8  = (nchunk * 8 + TB - 1) / TB;

    // dtype detect (reads <=8KB — in bounds under both interpretations)
    {
        int npairs = E;
        if (npairs > 1024) npairs = 1024;
        k_detect<<<1, 256>>>((const int2*)e32, npairs);
    }

    // zero out + z + degi; CSR build: hist -> scan(+dis) -> sort
    k_zero<<<gO, TB>>>(out, n4, N);
    k_hist<<<gE, TB>>>(e32, E, N);
    k_scan1<<<nb, SCAN_B>>>(N);
    k_scan2<<<1, 32>>>(nb);
    k_scan3<<<gN, TB>>>(N);
    k_sort<<<gE, TB>>>(e32, E, N);

    // y = A'x accumulated fp32 in out (segmented scatter)
    k_conv1<<<gC16, TB>>>(x, out, E, N);

    // two half-width passes: z = A'y (fp16 accum), then fused epilogue
    k_conv2<<<gC8, TB>>>(out, E, N, 0);
    k_final<<<gH, TB>>>(x, out, nh, 0);
    k_conv2<<<gC8, TB>>>(out, E, N, 8);
    k_final<<<gH, TB>>>(x, out, nh, 8);
}

// round 17
// speedup vs baseline: 1.8224x; 1.2004x over previous
#include <cuda_runtime.h>
#include <cuda_fp16.h>
#include <cstdint>

// ---------------------------------------------------------------------------
// LightGCN forward: out = (x + A'x + A'(A'x)) / 3
// per-edge norm (row->col): dis[row]*dis[col], dis = rsqrt(indeg) or 0.
// N = 150000, D = 64 fp32, E = 2,000,000 ([2,E], int64 OR int32, runtime-
// detected).
// Architecture: counting-sort edges by destination; convs run edge-parallel
// over fixed 64-edge chunks, register accumulation, REDG flush only at column
// boundaries (R14-16 proven). This round: single full-width conv2 gathering a
// 19.2MB fp16 copy of y and scattering fp32 v4-REDG directly into out
// (out pre-set to (x+y)/3) — no z accumulator, no final passes.
// Scratch ~29.0MB (probe: 20.4MB proven-safe, 39.6MB trips the mem check;
// hypothesis is a 32MiB granule boundary).
// ---------------------------------------------------------------------------

#define MAXN 150016
#define MAXE 2000000
#define SCAN_B 1024
#define NBLK_MAX ((MAXN + SCAN_B - 1) / SCAN_B)
#define CHUNK 64

// Scratch: ~29.0 MB total.
__device__ int   g_shift;                // 1 if edge dtype int64, 0 if int32
__device__ int   g_degi[MAXN];           // in-degree
__device__ int   g_cur[MAXN];            // excl offsets -> END offsets after sort
__device__ float g_dis[MAXN];
__device__ int   g_srow[MAXE];           // source row per edge, sorted by col (8MB)
__device__ uint2 g_yh[MAXN * 16];        // fp16x4 full-width copy of y (19.2MB)
__device__ int   g_bsum[NBLK_MAX];

// ---------------------------------------------------------------------------
__global__ void k_detect(const int2* __restrict__ p, int npairs) {
    __shared__ int nz;
    if (threadIdx.x == 0) nz = 0;
    __syncthreads();
    int local = 0;
    for (int i = threadIdx.x; i < npairs; i += blockDim.x)
        if (p[i].y != 0) local = 1;
    if (local) atomicOr(&nz, 1);
    __syncthreads();
    if (threadIdx.x == 0) g_shift = (nz == 0) ? 1 : 0;
}

__device__ __forceinline__ unsigned load_idx(const int* __restrict__ p32,
                                             long long pos, int shift) {
    return (unsigned)p32[pos << shift];
}

// Zero out (38.4MB) + degi. Grid covers n4 = N*16. (yh is fully written by
// k_mid before conv2 reads it — no zeroing needed.)
__global__ void k_zero(float4* __restrict__ out, int n4, int N) {
    int i = blockIdx.x * blockDim.x + threadIdx.x;
    if (i < N) g_degi[i] = 0;
    if (i < n4) out[i] = make_float4(0.f, 0.f, 0.f, 0.f);
}

__global__ void k_hist(const int* __restrict__ e32, int E, int N) {
    int i = blockIdx.x * blockDim.x + threadIdx.x;
    if (i >= E) return;
    int sh = g_shift;
    unsigned col = load_idx(e32, (long long)E + i, sh);
    if (col < (unsigned)N) atomicAdd(&g_degi[col], 1);
}

// Block-level exclusive scan via warp shuffles.
__global__ void k_scan1(int N) {
    __shared__ int warp_tot[SCAN_B / 32];
    int tid = threadIdx.x;
    int gid = blockIdx.x * SCAN_B + tid;
    int lane = tid & 31, wid = tid >> 5;
    int v = (gid < N) ? g_degi[gid] : 0;

    int s = v;
    #pragma unroll
    for (int off = 1; off < 32; off <<= 1) {
        int t = __shfl_up_sync(0xffffffffu, s, off);
        if (lane >= off) s += t;
    }
    if (lane == 31) warp_tot[wid] = s;
    __syncthreads();

    if (wid == 0) {
        int w = warp_tot[lane];
        int ws = w;
        #pragma unroll
        for (int off = 1; off < 32; off <<= 1) {
            int t = __shfl_up_sync(0xffffffffu, ws, off);
            if (lane >= off) ws += t;
        }
        warp_tot[lane] = ws - w;  // exclusive
    }
    __syncthreads();

    int incl = s + warp_tot[wid];
    if (gid < N) g_cur[gid] = incl - v;  // exclusive within block
    if (tid == SCAN_B - 1) g_bsum[blockIdx.x] = incl;
}

// One warp scans the block sums (shuffle scan in 32-chunks).
__global__ void k_scan2(int nb) {
    int lane = threadIdx.x;
    int run = 0;
    for (int base = 0; base < nb; base += 32) {
        int i = base + lane;
        int v = (i < nb) ? g_bsum[i] : 0;
        int s = v;
        #pragma unroll
        for (int off = 1; off < 32; off <<= 1) {
            int t = __shfl_up_sync(0xffffffffu, s, off);
            if (lane >= off) s += t;
        }
        if (i < nb) g_bsum[i] = run + s - v;  // exclusive
        run += __shfl_sync(0xffffffffu, s, 31);
    }
}

// scan3 + dis fused.
__global__ void k_scan3(int N) {
    int gid = blockIdx.x * blockDim.x + threadIdx.x;
    if (gid >= N) return;
    g_cur[gid] += g_bsum[gid / SCAN_B];
    int d = g_degi[gid];
    g_dis[gid] = (d > 0) ? rsqrtf((float)d) : 0.0f;
}

// Counting-sort scatter; afterwards g_cur[col] == END offset of col's run.
__global__ void k_sort(const int* __restrict__ e32, int E, int N) {
    int i = blockIdx.x * blockDim.x + threadIdx.x;
    if (i >= E) return;
    int sh = g_shift;
    unsigned row = load_idx(e32, i, sh);
    unsigned col = load_idx(e32, (long long)E + i, sh);
    if (row >= (unsigned)N || col >= (unsigned)N) return;
    int pos = atomicAdd(&g_cur[col], 1);
    g_srow[pos] = (int)row;
}

// Smallest col with end[col] > j.
__device__ __forceinline__ int find_col(int N, int j) {
    int lo = 0, hi = N - 1;
    while (lo < hi) {
        int mid = (lo + hi) >> 1;
        if (g_cur[mid] > j) hi = mid; else lo = mid + 1;
    }
    return lo;
}

// conv1: out[col] += dis[col] * sum(dis[row]*x[row]) over sorted runs.
// 16 lanes per 64-edge chunk; v4-REDG only at run boundaries.
__global__ void __launch_bounds__(256) k_conv1(
        const float4* __restrict__ x, float4* __restrict__ out, int E, int N) {
    int t = blockIdx.x * blockDim.x + threadIdx.x;
    int chunk = t >> 4, c = t & 15;
    int total = g_cur[N - 1];
    int s = chunk * CHUNK;
    if (s >= total) return;
    int e = s + CHUNK; if (e > total) e = total;

    int col = find_col(N, s);
    int bound = g_cur[col];
    int j = s;
    while (true) {
        int runend = bound < e ? bound : e;
        float4 acc = make_float4(0.f, 0.f, 0.f, 0.f);
        for (; j < runend; ++j) {
            int row = g_srow[j];
            float w = __ldg(&g_dis[row]);
            float4 v = __ldg(&x[(size_t)row * 16 + c]);
            acc.x += w * v.x; acc.y += w * v.y;
            acc.z += w * v.z; acc.w += w * v.w;
        }
        float dc = g_dis[col];
        float4* pd = &out[(size_t)col * 16 + c];
        asm volatile("red.global.add.v4.f32 [%0], {%1, %2, %3, %4};"
                     :: "l"(pd), "f"(acc.x * dc), "f"(acc.y * dc),
                        "f"(acc.z * dc), "f"(acc.w * dc) : "memory");
        if (j >= e) break;
        do { ++col; bound = g_cur[col]; } while (bound <= j);
    }
}

// mid: yh = fp16(y); out = (x + y) / 3.  (y = out after conv1)
__global__ void k_mid(const float4* __restrict__ x, float4* __restrict__ out,
                      int n4) {
    int i = blockIdx.x * blockDim.x + threadIdx.x;
    if (i >= n4) return;
    float4 y = out[i];
    __half2 h0 = __floats2half2_rn(y.x, y.y);
    __half2 h1 = __floats2half2_rn(y.z, y.w);
    uint2 h;
    h.x = *(const unsigned*)&h0;
    h.y = *(const unsigned*)&h1;
    g_yh[i] = h;
    float4 a = __ldg(&x[i]);
    const float s = 1.0f / 3.0f;
    out[i] = make_float4((a.x + y.x) * s, (a.y + y.y) * s,
                         (a.z + y.z) * s, (a.w + y.w) * s);
}

// conv2: out[col] += (dis[col]/3) * sum(dis[row]*y[row]), gathering y as
// fp16x4 (8B/lane) from g_yh; fp32 register accumulation; v4-REDG flush.
__global__ void __launch_bounds__(256) k_conv2(
        float4* __restrict__ out, int E, int N) {
    int t = blockIdx.x * blockDim.x + threadIdx.x;
    int chunk = t >> 4, c = t & 15;
    int total = g_cur[N - 1];
    int s = chunk * CHUNK;
    if (s >= total) return;
    int e = s + CHUNK; if (e > total) e = total;

    int col = find_col(N, s);
    int bound = g_cur[col];
    int j = s;
    while (true) {
        int runend = bound < e ? bound : e;
        float4 acc = make_float4(0.f, 0.f, 0.f, 0.f);
        for (; j < runend; ++j) {
            int row = g_srow[j];
            float w = __ldg(&g_dis[row]);
            uint2 h = __ldg(&g_yh[(size_t)row * 16 + c]);
            float2 f0 = __half22float2(*(const __half2*)&h.x);
            float2 f1 = __half22float2(*(const __half2*)&h.y);
            acc.x += w * f0.x; acc.y += w * f0.y;
            acc.z += w * f1.x; acc.w += w * f1.y;
        }
        float dc = g_dis[col] * (1.0f / 3.0f);
        float4* pd = &out[(size_t)col * 16 + c];
        asm volatile("red.global.add.v4.f32 [%0], {%1, %2, %3, %4};"
                     :: "l"(pd), "f"(acc.x * dc), "f"(acc.y * dc),
                        "f"(acc.z * dc), "f"(acc.w * dc) : "memory");
        if (j >= e) break;
        do { ++col; bound = g_cur[col]; } while (bound <= j);
    }
}

// ---------------------------------------------------------------------------
extern "C" void kernel_launch(void* const* d_in, const int* in_sizes, int n_in,
                              void* d_out, int out_size) {
    int ix = 0, ie = 1;
    if (n_in >= 2 && in_sizes[0] < in_sizes[1]) { ix = 1; ie = 0; }

    const float4* x   = (const float4*)d_in[ix];
    const int*    e32 = (const int*)d_in[ie];
    float4*       out = (float4*)d_out;

    int N = in_sizes[ix] / 64;
    int E = in_sizes[ie] / 2;
    if (N > MAXN) N = MAXN;
    if (E > MAXE) E = MAXE;

    const int TB = 256;
    const int n4 = N * 16;
    const int gO = (n4 + TB - 1) / TB;
    const int gN = (N + TB - 1) / TB;
    const int gE = (E + TB - 1) / TB;
    const int nb = (N + SCAN_B - 1) / SCAN_B;
    const int nchunk = (E + CHUNK - 1) / CHUNK;
    const int gC16 = (nchunk * 16 + TB - 1) / TB;

    // dtype detect (reads <=8KB — in bounds under both interpretations)
    {
        int npairs = E;
        if (npairs > 1024) npairs = 1024;
        k_detect<<<1, 256>>>((const int2*)e32, npairs);
    }

    // zero out + degi; CSR build: hist -> scan(+dis) -> sort
    k_zero<<<gO, TB>>>(out, n4, N);
    k_hist<<<gE, TB>>>(e32, E, N);
    k_scan1<<<nb, SCAN_B>>>(N);
    k_scan2<<<1, 32>>>(nb);
    k_scan3<<<gN, TB>>>(N);
    k_sort<<<gE, TB>>>(e32, E, N);

    // y = A'x (fp32, segmented scatter into out)
    k_conv1<<<gC16, TB>>>(x, out, E, N);

    // yh = fp16(y); out = (x+y)/3
    k_mid<<<gO, TB>>>(x, out, n4);

    // out += A'(y)/3 (fp16 gather, fp32 accumulate, segmented scatter)
    k_conv2<<<gC16, TB>>>(out, E, N);
}